// round 2
// baseline (speedup 1.0000x reference)
#include <cuda_runtime.h>

#define BN_EPS 1e-5f
#define NUM_GRAPHS 256

// ---------------- small folded-weight scratch (device globals) -----------------
__device__ float g_W1f[3 * 64];
__device__ float g_b1f[64];
__device__ float g_W23f[64 * 128];
__device__ float g_b23f[128];

// ordered-int encoding for float atomicMax (monotonic)
__device__ __forceinline__ unsigned encf(float f) {
    unsigned u = __float_as_uint(f);
    return (u & 0x80000000u) ? ~u : (u | 0x80000000u);
}

// ---------------- kernel 0: fold BN1 into layer1; fuse W2@W3 with BN3 ----------
__global__ void prep_kernel(const float* __restrict__ W1, const float* __restrict__ b1,
                            const float* __restrict__ g1, const float* __restrict__ be1,
                            const float* __restrict__ m1, const float* __restrict__ v1,
                            const float* __restrict__ W2, const float* __restrict__ b2,
                            const float* __restrict__ W3, const float* __restrict__ b3,
                            const float* __restrict__ g3, const float* __restrict__ be3,
                            const float* __restrict__ m3, const float* __restrict__ v3)
{
    __shared__ float W2s[64 * 64];
    int t = threadIdx.x;  // 128 threads
    for (int i = t; i < 64 * 64; i += 128) W2s[i] = W2[i];

    if (t < 64) {
        float s = g1[t] * rsqrtf(v1[t] + BN_EPS);
        for (int i = 0; i < 3; i++) g_W1f[i * 64 + t] = W1[i * 64 + t] * s;
        g_b1f[t] = (b1[t] - m1[t]) * s + be1[t];
    }

    // each thread owns one output column j = t of the fused 64->128 layer
    float w3c[64];
    #pragma unroll
    for (int k = 0; k < 64; k++) w3c[k] = W3[k * 128 + t];
    __syncthreads();

    float s3 = g3[t] * rsqrtf(v3[t] + BN_EPS);
    float accb = 0.f;
    #pragma unroll
    for (int k = 0; k < 64; k++) accb = fmaf(b2[k], w3c[k], accb);
    g_b23f[t] = (accb + b3[t] - m3[t]) * s3 + be3[t];

    for (int i = 0; i < 64; i++) {
        float acc = 0.f;
        #pragma unroll
        for (int k = 0; k < 64; k++) acc = fmaf(W2s[i * 64 + k], w3c[k], acc);
        g_W23f[i * 128 + t] = acc * s3;
    }
}

// ---------------- fused kernel: x -> h3 (smem) -> h3@W4 -> segmented max -------
// Block: 256 threads, tile = 128 points.
// smem: As = h3 [k=128][m=128] (64 KB), Bs = W4 tile [k=128][n=128] (64 KB, also
// reused as H (h1) + W23 in phase A and as Cs in the scan), + small constants.
__global__ void __launch_bounds__(256, 1)
fused_kernel(const float* __restrict__ x, const int* __restrict__ batch,
             const float* __restrict__ W4, const float* __restrict__ b4,
             unsigned* __restrict__ out_enc, int n)
{
    extern __shared__ float sm[];
    float* As   = sm;               // 16384 floats: h3, layout [k][m]
    float* Bs   = sm + 16384;       // 16384 floats: W4 tile [k][n] / scratch
    float* H    = Bs;               // phase A: h1 [k=64][m=128] (8192 floats)
    float* W23s = Bs + 8192;        // phase A: fused W23 [k=64][n=128] (8192 floats)
    float* xs   = sm + 32768;       // 384:  x, layout [c][m]
    float* w1s  = xs + 384;         // 192
    float* b1s  = w1s + 192;        // 64
    float* b23s = b1s + 64;         // 128
    float* b4s  = b23s + 128;       // 128
    int*   sb   = (int*)(b4s + 128);// 128 batch ids

    int t  = threadIdx.x;
    int p0 = blockIdx.x * 128;

    // ---- phase A loads ----
    { // W23f copy (L2-resident, 32 KB/block)
        const float4* src = (const float4*)g_W23f;
        float4* dst = (float4*)W23s;
        #pragma unroll
        for (int i = 0; i < 8; i++) dst[t + i * 256] = src[t + i * 256];
    }
    for (int i = t; i < 384; i += 256) {
        int p = i / 3, c = i - p * 3;
        xs[c * 128 + p] = (p0 + p < n) ? x[(size_t)(p0 + p) * 3 + c] : 0.f;
    }
    if (t < 192) w1s[t] = g_W1f[t];
    if (t < 64)  b1s[t] = g_b1f[t];
    if (t < 128) b23s[t] = g_b23f[t];
    if (t < 128) {
        int p = p0 + t;
        sb[t] = (p < n) ? batch[p] : -1;
    }
    __syncthreads();

    { // h1 = relu(BN-folded layer 1): each thread does 32 (k,m) values
        int m = t & 127, kh = (t >> 7) * 32;
        float x0 = xs[m], x1 = xs[128 + m], x2 = xs[256 + m];
        #pragma unroll
        for (int i = 0; i < 32; i++) {
            int k = kh + i;
            float v = fmaf(x0, w1s[k], fmaf(x1, w1s[64 + k], fmaf(x2, w1s[128 + k], b1s[k])));
            H[k * 128 + m] = fmaxf(v, 0.f);
        }
    }
    __syncthreads();

    int tx = t & 15, ty = t >> 4;
    int mb = ty * 8, nb = tx * 8;

    // ---- phase A GEMM: h3 = relu(H^T @ W23s + b23), 128x128x64, stored [k][m] ----
    {
        float acc[8][8];
        #pragma unroll
        for (int i = 0; i < 8; i++)
            #pragma unroll
            for (int j = 0; j < 8; j++) acc[i][j] = 0.f;

        const float4* H4 = (const float4*)H;
        const float4* B4 = (const float4*)W23s;
        #pragma unroll 1
        for (int k4 = 0; k4 < 16; k4++) {
            #pragma unroll
            for (int kk = 0; kk < 4; kk++) {
                int k = k4 * 4 + kk;
                float4 a0 = H4[k * 32 + (mb >> 2)];
                float4 a1 = H4[k * 32 + (mb >> 2) + 1];
                float4 c0 = B4[k * 32 + (nb >> 2)];
                float4 c1 = B4[k * 32 + (nb >> 2) + 1];
                float av[8] = {a0.x, a0.y, a0.z, a0.w, a1.x, a1.y, a1.z, a1.w};
                float bv[8] = {c0.x, c0.y, c0.z, c0.w, c1.x, c1.y, c1.z, c1.w};
                #pragma unroll
                for (int i = 0; i < 8; i++)
                    #pragma unroll
                    for (int j = 0; j < 8; j++)
                        acc[i][j] = fmaf(av[i], bv[j], acc[i][j]);
            }
        }
        __syncthreads();   // done reading H/W23s before As writes? (As is separate) —
                           // actually As is a distinct region; barrier only needed
                           // before Bs is overwritten in phase B. Keep it for safety.

        // store h3 transposed: As[k=h3feat][m=point], bias + relu
        #pragma unroll
        for (int j = 0; j < 8; j++) {
            float bj = b23s[nb + j];
            float4 o0, o1;
            o0.x = fmaxf(acc[0][j] + bj, 0.f);
            o0.y = fmaxf(acc[1][j] + bj, 0.f);
            o0.z = fmaxf(acc[2][j] + bj, 0.f);
            o0.w = fmaxf(acc[3][j] + bj, 0.f);
            o1.x = fmaxf(acc[4][j] + bj, 0.f);
            o1.y = fmaxf(acc[5][j] + bj, 0.f);
            o1.z = fmaxf(acc[6][j] + bj, 0.f);
            o1.w = fmaxf(acc[7][j] + bj, 0.f);
            float* dst = &As[(nb + j) * 128 + mb];
            ((float4*)dst)[0] = o0;
            ((float4*)dst)[1] = o1;
        }
    }
    __syncthreads();

    // ---- phase B: loop over 8 column tiles of W4; GEMM + segmented max --------
    const float4* As4 = (const float4*)As;
    #pragma unroll 1
    for (int nt = 0; nt < 8; nt++) {
        int n0 = nt * 128;

        { // Bs: W4[k=0..127][n0 .. n0+127]
            float4* dst = (float4*)Bs;
            #pragma unroll
            for (int i = 0; i < 16; i++) {
                int id = t + i * 256;
                int r = id >> 5, c4 = id & 31;
                dst[id] = *(const float4*)&W4[(size_t)r * 1024 + n0 + c4 * 4];
            }
        }
        if (t < 128) b4s[t] = b4[n0 + t];
        __syncthreads();

        float acc[8][8];
        #pragma unroll
        for (int i = 0; i < 8; i++)
            #pragma unroll
            for (int j = 0; j < 8; j++) acc[i][j] = 0.f;

        const float4* Bs4 = (const float4*)Bs;
        #pragma unroll 1
        for (int k4 = 0; k4 < 32; k4++) {
            #pragma unroll
            for (int kk = 0; kk < 4; kk++) {
                int k = k4 * 4 + kk;
                float4 a0 = As4[k * 32 + (mb >> 2)];
                float4 a1 = As4[k * 32 + (mb >> 2) + 1];
                float4 c0 = Bs4[k * 32 + (nb >> 2)];
                float4 c1 = Bs4[k * 32 + (nb >> 2) + 1];
                float av[8] = {a0.x, a0.y, a0.z, a0.w, a1.x, a1.y, a1.z, a1.w};
                float bv[8] = {c0.x, c0.y, c0.z, c0.w, c1.x, c1.y, c1.z, c1.w};
                #pragma unroll
                for (int i = 0; i < 8; i++)
                    #pragma unroll
                    for (int j = 0; j < 8; j++)
                        acc[i][j] = fmaf(av[i], bv[j], acc[i][j]);
            }
        }
        __syncthreads();   // all reads of Bs complete

        // dump C (no bias; bias commutes with max) into Bs region, row-major
        float* Cs = Bs;
        #pragma unroll
        for (int i = 0; i < 8; i++) {
            float4 o0, o1;
            o0.x = acc[i][0]; o0.y = acc[i][1]; o0.z = acc[i][2]; o0.w = acc[i][3];
            o1.x = acc[i][4]; o1.y = acc[i][5]; o1.z = acc[i][6]; o1.w = acc[i][7];
            ((float4*)&Cs[(mb + i) * 128 + nb])[0] = o0;
            ((float4*)&Cs[(mb + i) * 128 + nb])[1] = o1;
        }
        __syncthreads();

        // segmented max scan: each column scanned by 2 threads (64 rows each);
        // batch is sorted so runs are contiguous -> ~1-2 atomics per (col, block)
        {
            int col = t & 127;
            int mlo = (t >> 7) * 64;
            float bias = b4s[col];
            int cur = -2;
            float best = 0.f;
            for (int m = mlo; m < mlo + 64; m++) {
                int g = sb[m];
                float v = Cs[m * 128 + col];
                if (g != cur) {
                    if (cur >= 0)
                        atomicMax(&out_enc[cur * 1024 + n0 + col], encf(best + bias));
                    cur = g;
                    best = v;
                } else {
                    best = fmaxf(best, v);
                }
            }
            if (cur >= 0)
                atomicMax(&out_enc[cur * 1024 + n0 + col], encf(best + bias));
        }
        __syncthreads();   // scan done before next tile overwrites Bs
    }
}

// ---------------- init / decode ------------------------------------------------
__global__ void init_out(unsigned* out_enc, int total) {
    int i = blockIdx.x * 256 + threadIdx.x;
    if (i < total) out_enc[i] = 0x007FFFFFu;   // encf(-inf)
}

__global__ void decode_out(float* out, int total) {
    int i = blockIdx.x * 256 + threadIdx.x;
    if (i < total) {
        unsigned u = ((unsigned*)out)[i];
        unsigned d = (u & 0x80000000u) ? (u ^ 0x80000000u) : ~u;
        out[i] = __uint_as_float(d);
    }
}

// ---------------- launch -------------------------------------------------------
extern "C" void kernel_launch(void* const* d_in, const int* in_sizes, int n_in,
                              void* d_out, int out_size)
{
    const float* x     = (const float*)d_in[0];
    const int*   batch = (const int*)  d_in[1];
    const float* W1  = (const float*)d_in[2];
    const float* b1  = (const float*)d_in[3];
    const float* g1  = (const float*)d_in[4];
    const float* be1 = (const float*)d_in[5];
    const float* m1  = (const float*)d_in[6];
    const float* v1  = (const float*)d_in[7];
    const float* W2  = (const float*)d_in[8];
    const float* b2  = (const float*)d_in[9];
    const float* W3  = (const float*)d_in[10];
    const float* b3  = (const float*)d_in[11];
    const float* g3  = (const float*)d_in[12];
    const float* be3 = (const float*)d_in[13];
    const float* m3  = (const float*)d_in[14];
    const float* v3  = (const float*)d_in[15];
    const float* W4  = (const float*)d_in[16];
    const float* b4  = (const float*)d_in[17];

    int n  = in_sizes[0] / 3;
    int NT = (n + 127) / 128;

    // smem: 16384 + 16384 + 384 + 192 + 64 + 128 + 128 + 128(int) floats
    size_t smB = (size_t)(16384 + 16384 + 384 + 192 + 64 + 128 + 128 + 128) * 4;
    cudaFuncSetAttribute(fused_kernel, cudaFuncAttributeMaxDynamicSharedMemorySize, (int)smB);

    prep_kernel<<<1, 128>>>(W1, b1, g1, be1, m1, v1, W2, b2, W3, b3, g3, be3, m3, v3);

    int blocks_o = (out_size + 255) / 256;
    init_out<<<blocks_o, 256>>>((unsigned*)d_out, out_size);

    fused_kernel<<<NT, 256, smB>>>(x, batch, W4, b4, (unsigned*)d_out, n);

    decode_out<<<blocks_o, 256>>>((float*)d_out, out_size);
}

// round 4
// speedup vs baseline: 3.3605x; 3.3605x over previous
#include <cuda_runtime.h>
#include <cstdint>

#define BN_EPS 1e-5f
#define NUM_GRAPHS 256

#define P_A 132              // A (h3) smem pitch in floats
#define P_B 136              // B (W4 tile) pitch in floats
#define B_TILE_FLOATS (128 * P_B)          // 17408
#define B_TILE_BYTES  (B_TILE_FLOATS * 4)  // 69632

// ---------------- device-global scratch ----------------------------------------
__device__ float g_W1f[3 * 64];
__device__ float g_b1f[64];
__device__ float g_W23f[64 * 128];
__device__ float g_b23f[128];
// W4 pre-transposed to 8 per-N-tile padded images [k=128][n pitch 136], tf32-rounded
__device__ __align__(1024) float g_W4T[8 * B_TILE_FLOATS];

// ---------------- PTX helpers ---------------------------------------------------
__device__ __forceinline__ uint32_t smem_u32(const void* p) {
    uint32_t a;
    asm("{ .reg .u64 t; cvta.to.shared.u64 t, %1; cvt.u32.u64 %0, t; }" : "=r"(a) : "l"(p));
    return a;
}
#define MBAR_INIT(addr, cnt) \
    asm volatile("mbarrier.init.shared.b64 [%0], %1;" :: "r"(addr), "r"(cnt) : "memory")
#define MBAR_EXPECT_TX(addr, bytes) \
    asm volatile("mbarrier.arrive.expect_tx.shared.b64 _, [%0], %1;" :: "r"(addr), "r"(bytes) : "memory")
#define MBAR_WAIT(addr, phase) do { \
    asm volatile("{\n\t.reg .pred P;\n\tWL_%=:\n\t" \
        "mbarrier.try_wait.parity.acquire.cta.shared::cta.b64 P, [%0], %1, 0x989680;\n\t" \
        "@P bra.uni WD_%=;\n\tbra.uni WL_%=;\n\tWD_%=:\n\t}" \
        :: "r"(addr), "r"(phase) : "memory"); \
} while (0)
#define FENCE_ASYNC_SHARED() asm volatile("fence.proxy.async.shared::cta;" ::: "memory")

__device__ __forceinline__ void bulk_g2s(uint32_t dst, const void* src, uint32_t bytes, uint32_t mbar) {
    asm volatile("cp.async.bulk.shared::cta.global.mbarrier::complete_tx::bytes [%0], [%1], %2, [%3];"
                 :: "r"(dst), "l"(src), "r"(bytes), "r"(mbar) : "memory");
}

__device__ __forceinline__ uint32_t f2tf32(float x) {
    uint32_t u;
    asm("cvt.rna.tf32.f32 %0, %1;" : "=r"(u) : "f"(x));
    return u;
}

// tf32 mma: D(16x8) += A(16x8) * B(8x8), row.col
__device__ __forceinline__ void mma_tf32(float* c, const uint32_t* a, const uint32_t* b) {
    asm volatile("mma.sync.aligned.m16n8k8.row.col.f32.tf32.tf32.f32 "
                 "{%0,%1,%2,%3}, {%4,%5,%6,%7}, {%8,%9}, {%0,%1,%2,%3};"
                 : "+f"(c[0]), "+f"(c[1]), "+f"(c[2]), "+f"(c[3])
                 : "r"(a[0]), "r"(a[1]), "r"(a[2]), "r"(a[3]), "r"(b[0]), "r"(b[1]));
}

// ordered-int encoding for float atomicMax (monotonic)
__device__ __forceinline__ unsigned encf(float f) {
    unsigned u = __float_as_uint(f);
    return (u & 0x80000000u) ? ~u : (u | 0x80000000u);
}

// ---------------- kernel 0: fold BN1; fuse W2@W3 with BN3 ----------------------
__global__ void prep_kernel(const float* __restrict__ W1, const float* __restrict__ b1,
                            const float* __restrict__ g1, const float* __restrict__ be1,
                            const float* __restrict__ m1, const float* __restrict__ v1,
                            const float* __restrict__ W2, const float* __restrict__ b2,
                            const float* __restrict__ W3, const float* __restrict__ b3,
                            const float* __restrict__ g3, const float* __restrict__ be3,
                            const float* __restrict__ m3, const float* __restrict__ v3)
{
    __shared__ float W2s[64 * 64];
    int t = threadIdx.x;  // 128
    for (int i = t; i < 64 * 64; i += 128) W2s[i] = W2[i];

    if (t < 64) {
        float s = g1[t] * rsqrtf(v1[t] + BN_EPS);
        for (int i = 0; i < 3; i++) g_W1f[i * 64 + t] = W1[i * 64 + t] * s;
        g_b1f[t] = (b1[t] - m1[t]) * s + be1[t];
    }
    float w3c[64];
    #pragma unroll
    for (int k = 0; k < 64; k++) w3c[k] = W3[k * 128 + t];
    __syncthreads();

    float s3 = g3[t] * rsqrtf(v3[t] + BN_EPS);
    float accb = 0.f;
    #pragma unroll
    for (int k = 0; k < 64; k++) accb = fmaf(b2[k], w3c[k], accb);
    g_b23f[t] = (accb + b3[t] - m3[t]) * s3 + be3[t];

    for (int i = 0; i < 64; i++) {
        float acc = 0.f;
        #pragma unroll
        for (int k = 0; k < 64; k++) acc = fmaf(W2s[i * 64 + k], w3c[k], acc);
        g_W23f[i * 128 + t] = acc * s3;
    }
}

// ---------------- kernel 0b: W4 -> per-tile padded, tf32-rounded images --------
__global__ void w4t_kernel(const float* __restrict__ W4) {
    int id = blockIdx.x * 256 + threadIdx.x;   // 131072 total
    int nn = id & 1023, k = id >> 10;
    float v = W4[(size_t)k * 1024 + nn];
    int tile = nn >> 7, n = nn & 127;
    g_W4T[(size_t)tile * B_TILE_FLOATS + k * P_B + n] = __uint_as_float(f2tf32(v));
}

// ---------------- fused kernel --------------------------------------------------
// 256 threads (8 warps), 128 points/CTA.
// smem floats: As[0,16896) | B0[16896,34304) | B1[34304,51712) | red[51712,51968)
//              sb(int)[51968,52096) | aux[52096,53120) | mbars @float 53120
__global__ void __launch_bounds__(256, 1)
fused_kernel(const float* __restrict__ x, const int* __restrict__ batch,
             unsigned* __restrict__ out_enc, int n)
{
    extern __shared__ float sm[];
    float* As  = sm;                       // 128 x P_A
    float* B0  = sm + 16896;
    float* B1  = sm + 34304;
    float* red = sm + 51712;               // 2 x 128 fast-path stage
    int*   sb  = (int*)(sm + 51968);       // 128
    float* xs   = sm + 52096;              // 384
    float* w1s  = xs + 384;                // 192
    float* b1s  = w1s + 192;               // 64
    float* b23s = b1s + 64;                // 128
    // phase-A overlays inside As region:
    float* H    = As;                      // h1 [k=64][m=128]
    float* W23s = As + 8192;               // [k=64][n=128]

    uint32_t smem_base = smem_u32(sm);
    uint32_t barB0 = smem_base + 53120 * 4;
    uint32_t barB1 = barB0 + 8;
    uint32_t bAddr[2] = { smem_base + 16896 * 4, smem_base + 34304 * 4 };
    float* Bbuf[2] = { B0, B1 };

    int t    = threadIdx.x;
    int wid  = t >> 5;
    int lane = t & 31;
    int p0   = blockIdx.x * 128;

    if (t == 0) { MBAR_INIT(barB0, 1); MBAR_INIT(barB1, 1); }
    __syncthreads();
    FENCE_ASYNC_SHARED();

    // kick off B tiles 0,1 (buffers free during phase A)
    if (t == 0) {
        MBAR_EXPECT_TX(barB0, B_TILE_BYTES);
        bulk_g2s(bAddr[0], (const void*)(g_W4T + 0), B_TILE_BYTES, barB0);
        MBAR_EXPECT_TX(barB1, B_TILE_BYTES);
        bulk_g2s(bAddr[1], (const void*)(g_W4T + B_TILE_FLOATS), B_TILE_BYTES, barB1);
    }

    // ---- phase A loads ----
    {
        const float4* src = (const float4*)g_W23f;
        float4* dst = (float4*)W23s;
        #pragma unroll
        for (int i = 0; i < 8; i++) dst[t + i * 256] = src[t + i * 256];
    }
    for (int i = t; i < 384; i += 256) {
        int p = i / 3, c = i - p * 3;
        xs[c * 128 + p] = (p0 + p < n) ? x[(size_t)(p0 + p) * 3 + c] : 0.f;
    }
    if (t < 192) w1s[t] = g_W1f[t];
    if (t < 64)  b1s[t] = g_b1f[t];
    if (t < 128) b23s[t] = g_b23f[t];
    if (t < 128) {
        int p = p0 + t;
        sb[t] = (p < n) ? batch[p] : -1;
    }
    __syncthreads();

    { // h1 = relu(folded layer 1)
        int m = t & 127, kh = (t >> 7) * 32;
        float x0 = xs[m], x1 = xs[128 + m], x2 = xs[256 + m];
        #pragma unroll
        for (int i = 0; i < 32; i++) {
            int k = kh + i;
            float v = fmaf(x0, w1s[k], fmaf(x1, w1s[64 + k], fmaf(x2, w1s[128 + k], b1s[k])));
            H[k * 128 + m] = fmaxf(v, 0.f);
        }
    }
    __syncthreads();

    // ---- phase A GEMM: h3 = relu(H^T @ W23s + b23), tf32-rounded -> As[m][k] --
    {
        int tx = t & 15, ty = t >> 4;
        int mb = ty * 8, nb = tx * 8;
        float acc[8][8];
        #pragma unroll
        for (int i = 0; i < 8; i++)
            #pragma unroll
            for (int j = 0; j < 8; j++) acc[i][j] = 0.f;

        const float4* H4 = (const float4*)H;
        const float4* B4 = (const float4*)W23s;
        #pragma unroll 1
        for (int k4 = 0; k4 < 16; k4++) {
            #pragma unroll
            for (int kk = 0; kk < 4; kk++) {
                int k = k4 * 4 + kk;
                float4 a0 = H4[k * 32 + (mb >> 2)];
                float4 a1 = H4[k * 32 + (mb >> 2) + 1];
                float4 c0 = B4[k * 32 + (nb >> 2)];
                float4 c1 = B4[k * 32 + (nb >> 2) + 1];
                float av[8] = {a0.x, a0.y, a0.z, a0.w, a1.x, a1.y, a1.z, a1.w};
                float bv[8] = {c0.x, c0.y, c0.z, c0.w, c1.x, c1.y, c1.z, c1.w};
                #pragma unroll
                for (int i = 0; i < 8; i++)
                    #pragma unroll
                    for (int j = 0; j < 8; j++)
                        acc[i][j] = fmaf(av[i], bv[j], acc[i][j]);
            }
        }
        __syncthreads();   // all reads of H/W23s done before As overwritten

        #pragma unroll
        for (int i = 0; i < 8; i++) {
            uint32_t u[8];
            #pragma unroll
            for (int j = 0; j < 8; j++)
                u[j] = f2tf32(fmaxf(acc[i][j] + b23s[nb + j], 0.f));
            uint32_t* dst = (uint32_t*)&As[(mb + i) * P_A + nb];
            ((uint4*)dst)[0] = make_uint4(u[0], u[1], u[2], u[3]);
            ((uint4*)dst)[1] = make_uint4(u[4], u[5], u[6], u[7]);
        }
    }
    __syncthreads();

    // ---- phase B: 8 N-tiles of 128, tf32 mma.sync, double-buffered B ----------
    int mhalf = wid >> 2;            // 0/1: rows 0-63 / 64-127
    int nblk  = wid & 3;             // cols 32*nblk .. +32
    int r0 = lane >> 2, kq = lane & 3;
    const float* Aw = As + (mhalf * 64) * P_A;
    bool fast = (sb[0] >= 0) && (sb[0] == sb[127]);
    const float NEG_INF = __int_as_float(0xff800000);

    #pragma unroll 1
    for (int nt = 0; nt < 8; nt++) {
        int buf = nt & 1;
        MBAR_WAIT(buf ? barB1 : barB0, (nt >> 1) & 1);
        const float* Bw = Bbuf[buf] + nblk * 32;

        float acc[4][4][4];
        #pragma unroll
        for (int i = 0; i < 4; i++)
            #pragma unroll
            for (int j = 0; j < 4; j++)
                #pragma unroll
                for (int r = 0; r < 4; r++) acc[i][j][r] = 0.f;

        #pragma unroll 2
        for (int k8 = 0; k8 < 16; k8++) {
            int k0 = k8 * 8;
            uint32_t a[4][4];
            #pragma unroll
            for (int mbk = 0; mbk < 4; mbk++) {
                const uint32_t* ap = (const uint32_t*)&Aw[(mbk * 16 + r0) * P_A + k0 + kq];
                a[mbk][0] = ap[0];
                a[mbk][1] = ap[8 * P_A];
                a[mbk][2] = ap[4];
                a[mbk][3] = ap[8 * P_A + 4];
            }
            uint32_t b[4][2];
            #pragma unroll
            for (int nbk = 0; nbk < 4; nbk++) {
                const uint32_t* bp = (const uint32_t*)&Bw[(k0 + kq) * P_B + nbk * 8 + r0];
                b[nbk][0] = bp[0];
                b[nbk][1] = bp[4 * P_B];
            }
            #pragma unroll
            for (int mbk = 0; mbk < 4; mbk++)
                #pragma unroll
                for (int nbk = 0; nbk < 4; nbk++)
                    mma_tf32(acc[mbk][nbk], a[mbk], b[nbk]);
        }
        __syncthreads();   // all warps done reading B[buf]

        int n0 = nt * 128;
        if (fast) {
            // register-space column max over warp's 64 rows, then cross-warp via red
            #pragma unroll
            for (int nbk = 0; nbk < 4; nbk++) {
                float e = NEG_INF, o = NEG_INF;
                #pragma unroll
                for (int mbk = 0; mbk < 4; mbk++) {
                    e = fmaxf(e, fmaxf(acc[mbk][nbk][0], acc[mbk][nbk][2]));
                    o = fmaxf(o, fmaxf(acc[mbk][nbk][1], acc[mbk][nbk][3]));
                }
                #pragma unroll
                for (int d = 4; d <= 16; d <<= 1) {
                    e = fmaxf(e, __shfl_xor_sync(0xffffffffu, e, d));
                    o = fmaxf(o, __shfl_xor_sync(0xffffffffu, o, d));
                }
                if (r0 == 0) {
                    int c = nblk * 32 + nbk * 8 + kq * 2;
                    red[mhalf * 128 + c]     = e;
                    red[mhalf * 128 + c + 1] = o;
                }
            }
            __syncthreads();
            if (t < 128) {
                float v = fmaxf(red[t], red[128 + t]);
                atomicMax(&out_enc[(size_t)sb[0] * 1024 + n0 + t], encf(v));
            }
            __syncthreads();
        } else {
            // slow path: stage C into freed B[buf], run-scan columns
            float* Cs = Bbuf[buf];
            #pragma unroll
            for (int mbk = 0; mbk < 4; mbk++) {
                #pragma unroll
                for (int rr = 0; rr < 2; rr++) {
                    int r = mhalf * 64 + mbk * 16 + r0 + rr * 8;
                    #pragma unroll
                    for (int nbk = 0; nbk < 4; nbk++) {
                        int c = nblk * 32 + nbk * 8 + kq * 2;
                        float2 v = make_float2(acc[mbk][nbk][rr * 2], acc[mbk][nbk][rr * 2 + 1]);
                        *(float2*)&Cs[r * P_B + c] = v;
                    }
                }
            }
            __syncthreads();
            {
                int col = t & 127, half = t >> 7;
                int cur = -2; float best = 0.f;
                unsigned* obase = &out_enc[n0 + col];
                for (int m = half * 64; m < half * 64 + 64; m++) {
                    int g = sb[m];
                    float v = Cs[m * P_B + col];
                    if (g != cur) {
                        if (cur >= 0) atomicMax(obase + (size_t)cur * 1024, encf(best));
                        cur = g; best = v;
                    } else best = fmaxf(best, v);
                }
                if (cur >= 0) atomicMax(obase + (size_t)cur * 1024, encf(best));
            }
            __syncthreads();
        }

        // prefetch tile nt+2 into freed buffer
        if (t == 0 && nt + 2 < 8) {
            uint32_t bb = buf ? barB1 : barB0;
            MBAR_EXPECT_TX(bb, B_TILE_BYTES);
            bulk_g2s(bAddr[buf], (const void*)(g_W4T + (size_t)(nt + 2) * B_TILE_FLOATS),
                     B_TILE_BYTES, bb);
        }
    }
}

// ---------------- init / decode ------------------------------------------------
__global__ void init_out(unsigned* out_enc, int total) {
    int i = blockIdx.x * 256 + threadIdx.x;
    if (i < total) out_enc[i] = 0x007FFFFFu;   // encf(-inf)
}

__global__ void decode_out(float* out, const float* __restrict__ b4, int total) {
    int i = blockIdx.x * 256 + threadIdx.x;
    if (i < total) {
        unsigned u = ((unsigned*)out)[i];
        unsigned d = (u & 0x80000000u) ? (u ^ 0x80000000u) : ~u;
        out[i] = __uint_as_float(d) + b4[i & 1023];
    }
}

// ---------------- launch -------------------------------------------------------
extern "C" void kernel_launch(void* const* d_in, const int* in_sizes, int n_in,
                              void* d_out, int out_size)
{
    const float* x     = (const float*)d_in[0];
    const int*   batch = (const int*)  d_in[1];
    const float* W1  = (const float*)d_in[2];
    const float* b1  = (const float*)d_in[3];
    const float* g1  = (const float*)d_in[4];
    const float* be1 = (const float*)d_in[5];
    const float* m1  = (const float*)d_in[6];
    const float* v1  = (const float*)d_in[7];
    const float* W2  = (const float*)d_in[8];
    const float* b2  = (const float*)d_in[9];
    const float* W3  = (const float*)d_in[10];
    const float* b3  = (const float*)d_in[11];
    const float* g3  = (const float*)d_in[12];
    const float* be3 = (const float*)d_in[13];
    const float* m3  = (const float*)d_in[14];
    const float* v3  = (const float*)d_in[15];
    const float* W4  = (const float*)d_in[16];
    const float* b4  = (const float*)d_in[17];

    int n  = in_sizes[0] / 3;
    int NT = (n + 127) / 128;

    size_t smB = (53120 + 4) * 4;   // 212496 B (+pad)
    cudaFuncSetAttribute(fused_kernel, cudaFuncAttributeMaxDynamicSharedMemorySize, (int)smB);

    prep_kernel<<<1, 128>>>(W1, b1, g1, be1, m1, v1, W2, b2, W3, b3, g3, be3, m3, v3);
    w4t_kernel<<<512, 256>>>(W4);

    int blocks_o = (out_size + 255) / 256;
    init_out<<<blocks_o, 256>>>((unsigned*)d_out, out_size);

    fused_kernel<<<NT, 256, smB>>>(x, batch, (unsigned*)d_out, n);

    decode_out<<<blocks_o, 256>>>((float*)d_out, b4, out_size);
}

// round 5
// speedup vs baseline: 3.9674x; 1.1806x over previous
#include <cuda_runtime.h>
#include <cstdint>

#define BN_EPS 1e-5f
#define NUM_GRAPHS 256

#define P_A 132                       // As row pitch (floats); 132%32=4 -> conflict-free frags
#define SLAB 132                      // pair-layout slab stride (pairs); 132%16=4 -> LDS.64 ok
#define BT_FLOATS (16 * 4 * SLAB * 2) // 16896 floats per 128-col W4 tile
#define BT_BYTES  (BT_FLOATS * 4)     // 67584
#define W23P_FLOATS (8 * 4 * SLAB * 2) // 8448
#define W23P_BYTES (W23P_FLOATS * 4)   // 33792

// ---------------- device-global scratch ----------------------------------------
__device__ float g_W1f[3 * 64];
__device__ float g_b1f[64];
__device__ float g_b23f[128];
__device__ __align__(16) float g_W23p[W23P_FLOATS];        // W23 pair-layout, tf32
__device__ __align__(16) float g_W4T[8 * BT_FLOATS];       // W4 per-tile pair-layout, tf32

// ---------------- PTX helpers ---------------------------------------------------
__device__ __forceinline__ uint32_t smem_u32(const void* p) {
    uint32_t a;
    asm("{ .reg .u64 t; cvta.to.shared.u64 t, %1; cvt.u32.u64 %0, t; }" : "=r"(a) : "l"(p));
    return a;
}
#define MBAR_INIT(addr, cnt) \
    asm volatile("mbarrier.init.shared.b64 [%0], %1;" :: "r"(addr), "r"(cnt) : "memory")
#define MBAR_EXPECT_TX(addr, bytes) \
    asm volatile("mbarrier.arrive.expect_tx.shared.b64 _, [%0], %1;" :: "r"(addr), "r"(bytes) : "memory")
#define MBAR_WAIT(addr, phase) do { \
    asm volatile("{\n\t.reg .pred P;\n\tWL_%=:\n\t" \
        "mbarrier.try_wait.parity.acquire.cta.shared::cta.b64 P, [%0], %1, 0x989680;\n\t" \
        "@P bra.uni WD_%=;\n\tbra.uni WL_%=;\n\tWD_%=:\n\t}" \
        :: "r"(addr), "r"(phase) : "memory"); \
} while (0)
#define FENCE_ASYNC_SHARED() asm volatile("fence.proxy.async.shared::cta;" ::: "memory")

__device__ __forceinline__ void bulk_g2s(uint32_t dst, const void* src, uint32_t bytes, uint32_t mbar) {
    asm volatile("cp.async.bulk.shared::cta.global.mbarrier::complete_tx::bytes [%0], [%1], %2, [%3];"
                 :: "r"(dst), "l"(src), "r"(bytes), "r"(mbar) : "memory");
}

__device__ __forceinline__ uint32_t f2tf32(float x) {
    uint32_t u;
    asm("cvt.rna.tf32.f32 %0, %1;" : "=r"(u) : "f"(x));
    return u;
}

// tf32 mma: D(16x8) += A(16x8) * B(8x8), row.col
__device__ __forceinline__ void mma_tf32(float* c, const uint32_t* a, uint32_t b0, uint32_t b1) {
    asm volatile("mma.sync.aligned.m16n8k8.row.col.f32.tf32.tf32.f32 "
                 "{%0,%1,%2,%3}, {%4,%5,%6,%7}, {%8,%9}, {%0,%1,%2,%3};"
                 : "+f"(c[0]), "+f"(c[1]), "+f"(c[2]), "+f"(c[3])
                 : "r"(a[0]), "r"(a[1]), "r"(a[2]), "r"(a[3]), "r"(b0), "r"(b1));
}

__device__ __forceinline__ unsigned encf(float f) {
    unsigned u = __float_as_uint(f);
    return (u & 0x80000000u) ? ~u : (u | 0x80000000u);
}

// ---------------- kernel 0: fold BN1; fuse W2@W3 (+BN3) -> pair layout ----------
__global__ void prep_kernel(const float* __restrict__ W1, const float* __restrict__ b1,
                            const float* __restrict__ g1, const float* __restrict__ be1,
                            const float* __restrict__ m1, const float* __restrict__ v1,
                            const float* __restrict__ W2, const float* __restrict__ b2,
                            const float* __restrict__ W3, const float* __restrict__ b3,
                            const float* __restrict__ g3, const float* __restrict__ be3,
                            const float* __restrict__ m3, const float* __restrict__ v3)
{
    __shared__ float W2s[64 * 64];
    int t = threadIdx.x;  // 128
    for (int i = t; i < 64 * 64; i += 128) W2s[i] = W2[i];

    if (t < 64) {
        float s = g1[t] * rsqrtf(v1[t] + BN_EPS);
        for (int i = 0; i < 3; i++) g_W1f[i * 64 + t] = W1[i * 64 + t] * s;
        g_b1f[t] = (b1[t] - m1[t]) * s + be1[t];
    }
    float w3c[64];
    #pragma unroll
    for (int k = 0; k < 64; k++) w3c[k] = W3[k * 128 + t];
    __syncthreads();

    float s3 = g3[t] * rsqrtf(v3[t] + BN_EPS);
    float accb = 0.f;
    #pragma unroll
    for (int k = 0; k < 64; k++) accb = fmaf(b2[k], w3c[k], accb);
    g_b23f[t] = (accb + b3[t] - m3[t]) * s3 + be3[t];

    // fused W23[k][n=t], tf32-rounded, pair layout: ((k8*4+kq)*SLAB + n)*2 + h
    for (int k = 0; k < 64; k++) {
        float acc = 0.f;
        #pragma unroll
        for (int kk = 0; kk < 64; kk++) acc = fmaf(W2s[k * 64 + kk], w3c[kk], acc);
        int k8 = k >> 3, kq = k & 3, h = (k & 7) >> 2;
        g_W23p[(((k8 * 4 + kq) * SLAB) + t) * 2 + h] = __uint_as_float(f2tf32(acc * s3));
    }
}

// ---------------- kernel 0b: W4 -> per-tile pair-layout tf32 images -------------
__global__ void w4t_kernel(const float* __restrict__ W4) {
    int id = blockIdx.x * 256 + threadIdx.x;   // 131072
    int nn = id & 1023, k = id >> 10;
    float v = W4[(size_t)k * 1024 + nn];
    int tile = nn >> 7, n = nn & 127;
    int k8 = k >> 3, kq = k & 3, h = (k & 7) >> 2;
    g_W4T[(size_t)tile * BT_FLOATS + (((k8 * 4 + kq) * SLAB) + n) * 2 + h] =
        __uint_as_float(f2tf32(v));
}

// ---------------- fused kernel --------------------------------------------------
// 256 threads (8 warps), 128 points/CTA.
// smem floats: As[0,16896) | B0[16896,33792) | B1[33792,50688) (W23p overlays B1)
//   red[50688,50944) | xs[50944,51328) | w1s[51328,51520) | b1s[51520,51584)
//   b23s[51584,51712) | sb(int)[51712,51840) | mbars @51840
__global__ void __launch_bounds__(256, 1)
fused_kernel(const float* __restrict__ x, const int* __restrict__ batch,
             unsigned* __restrict__ out_enc, int n)
{
    extern __shared__ float sm[];
    float* As   = sm;
    float* B0   = sm + 16896;
    float* B1   = sm + 33792;
    float* red  = sm + 50688;
    float* xs   = sm + 50944;
    float* w1s  = sm + 51328;
    float* b1s  = sm + 51520;
    float* b23s = sm + 51584;
    int*   sb   = (int*)(sm + 51712);

    uint32_t smem_base = smem_u32(sm);
    uint32_t barB0 = smem_base + 51840 * 4;
    uint32_t barB1 = barB0 + 8;
    uint32_t bAddr[2] = { smem_base + 16896 * 4, smem_base + 33792 * 4 };
    float* Bbuf[2] = { B0, B1 };

    int t    = threadIdx.x;
    int wid  = t >> 5;
    int lane = t & 31;
    int p0   = blockIdx.x * 128;
    int mhalf = wid >> 2;            // rows mhalf*64 .. +63
    int nblk  = wid & 3;             // cols nblk*32 .. +31
    int r0 = lane >> 2, kq = lane & 3;

    if (t == 0) { MBAR_INIT(barB0, 1); MBAR_INIT(barB1, 1); }
    __syncthreads();
    FENCE_ASYNC_SHARED();

    if (t == 0) {
        MBAR_EXPECT_TX(barB0, BT_BYTES);
        bulk_g2s(bAddr[0], (const void*)g_W4T, BT_BYTES, barB0);
        MBAR_EXPECT_TX(barB1, W23P_BYTES);
        bulk_g2s(bAddr[1], (const void*)g_W23p, W23P_BYTES, barB1);
    }

    // ---- small loads ----
    for (int i = t; i < 384; i += 256) {
        int p = i / 3, c = i - p * 3;
        xs[c * 128 + p] = (p0 + p < n) ? x[(size_t)(p0 + p) * 3 + c] : 0.f;
    }
    if (t < 192) w1s[t] = g_W1f[t];
    if (t < 64)  b1s[t] = g_b1f[t];
    if (t < 128) b23s[t] = g_b23f[t];
    if (t < 128) {
        int p = p0 + t;
        sb[t] = (p < n) ? batch[p] : -1;
    }
    __syncthreads();

    // preload x for this thread's 8 rows
    float xr[8][3];
    #pragma unroll
    for (int mbk = 0; mbk < 4; mbk++)
        #pragma unroll
        for (int j = 0; j < 2; j++) {
            int row = mhalf * 64 + mbk * 16 + r0 + 8 * j;
            xr[mbk * 2 + j][0] = xs[row];
            xr[mbk * 2 + j][1] = xs[128 + row];
            xr[mbk * 2 + j][2] = xs[256 + row];
        }

    // ---- phase A: h3 = relu(h1 @ W23 + b23) via tf32 mma, h1 built in regs ----
    MBAR_WAIT(barB1, 0);   // W23p ready
    {
        float acc[4][4][4];
        #pragma unroll
        for (int i = 0; i < 4; i++)
            #pragma unroll
            for (int j = 0; j < 4; j++)
                #pragma unroll
                for (int r = 0; r < 4; r++) acc[i][j][r] = 0.f;

        const float2* Wp = (const float2*)B1;
        #pragma unroll 2
        for (int k8 = 0; k8 < 8; k8++) {
            int k1 = k8 * 8 + kq, k2 = k1 + 4;
            float wa0 = w1s[k1], wa1 = w1s[64 + k1], wa2 = w1s[128 + k1], ba = b1s[k1];
            float wb0 = w1s[k2], wb1 = w1s[64 + k2], wb2 = w1s[128 + k2], bb = b1s[k2];
            uint32_t a[4][4];
            #pragma unroll
            for (int mbk = 0; mbk < 4; mbk++) {
                #pragma unroll
                for (int j = 0; j < 2; j++) {
                    const float* xv = xr[mbk * 2 + j];
                    float va = fmaf(xv[0], wa0, fmaf(xv[1], wa1, fmaf(xv[2], wa2, ba)));
                    float vb = fmaf(xv[0], wb0, fmaf(xv[1], wb1, fmaf(xv[2], wb2, bb)));
                    a[mbk][j]     = f2tf32(fmaxf(va, 0.f));
                    a[mbk][j + 2] = f2tf32(fmaxf(vb, 0.f));
                }
            }
            #pragma unroll
            for (int nbk = 0; nbk < 4; nbk++) {
                float2 bv = Wp[(k8 * 4 + kq) * SLAB + nblk * 32 + nbk * 8 + r0];
                uint32_t b0 = __float_as_uint(bv.x), b1v = __float_as_uint(bv.y);
                #pragma unroll
                for (int mbk = 0; mbk < 4; mbk++)
                    mma_tf32(acc[mbk][nbk], a[mbk], b0, b1v);
            }
        }

        // epilogue: bias + relu + tf32, write As[m][k] pitch P_A
        #pragma unroll
        for (int mbk = 0; mbk < 4; mbk++) {
            int ra = mhalf * 64 + mbk * 16 + r0;
            #pragma unroll
            for (int nbk = 0; nbk < 4; nbk++) {
                int c0 = nblk * 32 + nbk * 8 + kq * 2;
                float bb0 = b23s[c0], bb1 = b23s[c0 + 1];
                uint2 v0, v1;
                v0.x = f2tf32(fmaxf(acc[mbk][nbk][0] + bb0, 0.f));
                v0.y = f2tf32(fmaxf(acc[mbk][nbk][1] + bb1, 0.f));
                v1.x = f2tf32(fmaxf(acc[mbk][nbk][2] + bb0, 0.f));
                v1.y = f2tf32(fmaxf(acc[mbk][nbk][3] + bb1, 0.f));
                *(uint2*)&As[ra * P_A + c0]       = v0;
                *(uint2*)&As[(ra + 8) * P_A + c0] = v1;
            }
        }
    }
    __syncthreads();          // As ready; W23p reads done
    if (t == 0) {             // B1 <- tile 1
        FENCE_ASYNC_SHARED();
        MBAR_EXPECT_TX(barB1, BT_BYTES);
        bulk_g2s(bAddr[1], (const void*)(g_W4T + BT_FLOATS), BT_BYTES, barB1);
    }

    // ---- phase B: 8 N-tiles, tf32 mma, double-buffered B ----
    bool fast = (sb[0] >= 0) && (sb[0] == sb[127]);
    const float NEG_INF = __int_as_float(0xff800000);
    const uint32_t* Asu = (const uint32_t*)As;

    #pragma unroll 1
    for (int nt = 0; nt < 8; nt++) {
        int buf = nt & 1;
        int parity = ((nt >> 1) & 1) ^ buf;
        MBAR_WAIT(buf ? barB1 : barB0, parity);
        const float2* Bp = (const float2*)Bbuf[buf];

        float acc[4][4][4];
        #pragma unroll
        for (int i = 0; i < 4; i++)
            #pragma unroll
            for (int j = 0; j < 4; j++)
                #pragma unroll
                for (int r = 0; r < 4; r++) acc[i][j][r] = 0.f;

        #pragma unroll 2
        for (int k8 = 0; k8 < 16; k8++) {
            int k0 = k8 * 8;
            uint32_t a[4][4];
            #pragma unroll
            for (int mbk = 0; mbk < 4; mbk++) {
                const uint32_t* ap = &Asu[(mhalf * 64 + mbk * 16 + r0) * P_A + k0 + kq];
                a[mbk][0] = ap[0];
                a[mbk][1] = ap[8 * P_A];
                a[mbk][2] = ap[4];
                a[mbk][3] = ap[8 * P_A + 4];
            }
            #pragma unroll
            for (int nbk = 0; nbk < 4; nbk++) {
                float2 bv = Bp[(k8 * 4 + kq) * SLAB + nblk * 32 + nbk * 8 + r0];
                uint32_t b0 = __float_as_uint(bv.x), b1v = __float_as_uint(bv.y);
                #pragma unroll
                for (int mbk = 0; mbk < 4; mbk++)
                    mma_tf32(acc[mbk][nbk], a[mbk], b0, b1v);
            }
        }
        __syncthreads();   // all warps done reading B[buf]

        int n0 = nt * 128;
        if (fast) {
            if (t == 0 && nt + 2 < 8) {    // prefetch immediately; fast path won't touch buf
                FENCE_ASYNC_SHARED();
                uint32_t bb = buf ? barB1 : barB0;
                MBAR_EXPECT_TX(bb, BT_BYTES);
                bulk_g2s(bAddr[buf], (const void*)(g_W4T + (size_t)(nt + 2) * BT_FLOATS),
                         BT_BYTES, bb);
            }
            #pragma unroll
            for (int nbk = 0; nbk < 4; nbk++) {
                float e = NEG_INF, o = NEG_INF;
                #pragma unroll
                for (int mbk = 0; mbk < 4; mbk++) {
                    e = fmaxf(e, fmaxf(acc[mbk][nbk][0], acc[mbk][nbk][2]));
                    o = fmaxf(o, fmaxf(acc[mbk][nbk][1], acc[mbk][nbk][3]));
                }
                #pragma unroll
                for (int d = 4; d <= 16; d <<= 1) {
                    e = fmaxf(e, __shfl_xor_sync(0xffffffffu, e, d));
                    o = fmaxf(o, __shfl_xor_sync(0xffffffffu, o, d));
                }
                if (r0 == 0) {
                    int c = nblk * 32 + nbk * 8 + kq * 2;
                    red[mhalf * 128 + c]     = e;
                    red[mhalf * 128 + c + 1] = o;
                }
            }
            __syncthreads();
            if (t < 128) {
                float v = fmaxf(red[t], red[128 + t]);
                atomicMax(&out_enc[(size_t)sb[0] * 1024 + n0 + t], encf(v));
            }
            __syncthreads();
        } else {
            // slow path: stage C into freed B[buf] (pitch P_A), run-scan columns
            float* Cs = Bbuf[buf];
            #pragma unroll
            for (int mbk = 0; mbk < 4; mbk++) {
                int ra = mhalf * 64 + mbk * 16 + r0;
                #pragma unroll
                for (int nbk = 0; nbk < 4; nbk++) {
                    int c0 = nblk * 32 + nbk * 8 + kq * 2;
                    *(float2*)&Cs[ra * P_A + c0]       = make_float2(acc[mbk][nbk][0], acc[mbk][nbk][1]);
                    *(float2*)&Cs[(ra + 8) * P_A + c0] = make_float2(acc[mbk][nbk][2], acc[mbk][nbk][3]);
                }
            }
            __syncthreads();
            {
                int col = t & 127, half = t >> 7;
                int cur = -2; float best = 0.f;
                unsigned* obase = &out_enc[n0 + col];
                for (int m = half * 64; m < half * 64 + 64; m++) {
                    int g = sb[m];
                    float v = Cs[m * P_A + col];
                    if (g != cur) {
                        if (cur >= 0) atomicMax(obase + (size_t)cur * 1024, encf(best));
                        cur = g; best = v;
                    } else best = fmaxf(best, v);
                }
                if (cur >= 0) atomicMax(obase + (size_t)cur * 1024, encf(best));
            }
            __syncthreads();
            if (t == 0 && nt + 2 < 8) {
                FENCE_ASYNC_SHARED();
                uint32_t bb = buf ? barB1 : barB0;
                MBAR_EXPECT_TX(bb, BT_BYTES);
                bulk_g2s(bAddr[buf], (const void*)(g_W4T + (size_t)(nt + 2) * BT_FLOATS),
                         BT_BYTES, bb);
            }
        }
    }
}

// ---------------- init / decode ------------------------------------------------
__global__ void init_out(unsigned* out_enc, int total) {
    int i = blockIdx.x * 256 + threadIdx.x;
    if (i < total) out_enc[i] = 0x007FFFFFu;   // encf(-inf)
}

__global__ void decode_out(float* out, const float* __restrict__ b4, int total) {
    int i = blockIdx.x * 256 + threadIdx.x;
    if (i < total) {
        unsigned u = ((unsigned*)out)[i];
        unsigned d = (u & 0x80000000u) ? (u ^ 0x80000000u) : ~u;
        out[i] = __uint_as_float(d) + b4[i & 1023];
    }
}

// ---------------- launch -------------------------------------------------------
extern "C" void kernel_launch(void* const* d_in, const int* in_sizes, int n_in,
                              void* d_out, int out_size)
{
    const float* x     = (const float*)d_in[0];
    const int*   batch = (const int*)  d_in[1];
    const float* W1  = (const float*)d_in[2];
    const float* b1  = (const float*)d_in[3];
    const float* g1  = (const float*)d_in[4];
    const float* be1 = (const float*)d_in[5];
    const float* m1  = (const float*)d_in[6];
    const float* v1  = (const float*)d_in[7];
    const float* W2  = (const float*)d_in[8];
    const float* b2  = (const float*)d_in[9];
    const float* W3  = (const float*)d_in[10];
    const float* b3  = (const float*)d_in[11];
    const float* g3  = (const float*)d_in[12];
    const float* be3 = (const float*)d_in[13];
    const float* m3  = (const float*)d_in[14];
    const float* v3  = (const float*)d_in[15];
    const float* W4  = (const float*)d_in[16];
    const float* b4  = (const float*)d_in[17];

    int n  = in_sizes[0] / 3;
    int NT = (n + 127) / 128;

    size_t smB = (51840 + 8) * 4;   // 207392 B
    cudaFuncSetAttribute(fused_kernel, cudaFuncAttributeMaxDynamicSharedMemorySize, (int)smB);

    prep_kernel<<<1, 128>>>(W1, b1, g1, be1, m1, v1, W2, b2, W3, b3, g3, be3, m3, v3);
    w4t_kernel<<<512, 256>>>(W4);

    int blocks_o = (out_size + 255) / 256;
    init_out<<<blocks_o, 256>>>((unsigned*)d_out, out_size);

    fused_kernel<<<NT, 256, smB>>>(x, batch, (unsigned*)d_out, n);

    decode_out<<<blocks_o, 256>>>((float*)d_out, b4, out_size);
}